// round 13
// baseline (speedup 1.0000x reference)
#include <cuda_runtime.h>
#include <cstddef>

// CRF NLL: emissions (B,S,T) f32, tags (B,S) int32-staged, mask (B,S) f32,
// transitions (T,T) f32, start_transitions (T) f32, end_transitions (T) f32
// out: scalar f32 = sum_b (partition_b - score_b)
#define B_SZ 512
#define S_SZ 1024
#define T_SZ 32
#define FULL 0xFFFFFFFFu
#define LN2F 0.69314718055994530942f

__device__ float    g_res[B_SZ];
__device__ unsigned g_cnt;   // zero-init; reset by last block each launch

// 2^-floor(log2(max over warp of w)) as (scale, exponent k), exact power of 2
__device__ __forceinline__ void scale_from_max(float w, float& sc, int& k)
{
    float mx = w;
#pragma unroll
    for (int o = 16; o > 0; o >>= 1)
        mx = fmaxf(mx, __shfl_xor_sync(FULL, mx, o));
    const int e = (int)((__float_as_uint(mx) >> 23) & 0xFF);
    sc = __uint_as_float((unsigned)(254 - e) << 23);   // 2^(127-e)
    k  = e - 127;
}

// One recursion step for both batches (interleaved chains fill each other's
// stall cycles on the warp's private SMSP). u = ring slot (compile-time 0..7),
// read parity u&1, write parity (u+1)&1. RENORM applies the scale computed
// 4 steps earlier, then launches the next scale computation (lag pipeline).
#define STEP(u, PREFETCH, RENORM, s_)                                          \
    {                                                                          \
        const float e0 = ee0[u], e1 = ee1[u];                                  \
        const float mA = mk0[u], mB = mk1[u];                                  \
        if (PREFETCH) {                                                        \
            ee0[u] = __expf(__ldg(emb0 + (size_t)((s_) + 8) * T_SZ + lane));   \
            ee1[u] = __expf(__ldg(emb1 + (size_t)((s_) + 8) * T_SZ + lane));   \
            mk0[u] = __ldg(mb0 + ((s_) + 8));                                  \
            mk1[u] = __ldg(mb1 + ((s_) + 8));                                  \
        }                                                                      \
        __syncwarp();                                                          \
        const float4* rp0 = ((u) & 1) ? rd0b : rd0a;                           \
        const float4* rp1 = ((u) & 1) ? rd1b : rd1a;                           \
        float a0[8], a1[8];                                                    \
        _Pragma("unroll")                                                      \
        for (int c = 0; c < 8; ++c) {                                          \
            const float4 W0 = rp0[c];                                          \
            const float4 W1 = rp1[c];                                          \
            float x0 = W0.x * et[4*c+0];                                       \
            float x1 = W1.x * et[4*c+0];                                       \
            x0 = fmaf(W0.y, et[4*c+1], x0); x1 = fmaf(W1.y, et[4*c+1], x1);    \
            x0 = fmaf(W0.z, et[4*c+2], x0); x1 = fmaf(W1.z, et[4*c+2], x1);    \
            x0 = fmaf(W0.w, et[4*c+3], x0); x1 = fmaf(W1.w, et[4*c+3], x1);    \
            a0[c] = x0; a1[c] = x1;                                            \
        }                                                                      \
        const float dot0 = ((a0[0]+a0[1])+(a0[2]+a0[3]))                       \
                         + ((a0[4]+a0[5])+(a0[6]+a0[7]));                      \
        const float dot1 = ((a1[0]+a1[1])+(a1[2]+a1[3]))                       \
                         + ((a1[4]+a1[5])+(a1[6]+a1[7]));                      \
        const float wn0 = dot0 * e0;                                           \
        const float wn1 = dot1 * e1;                                           \
        w0 = (mA != 0.0f) ? wn0 : w0;   /* exact: m is 0 or 1 */               \
        w1 = (mB != 0.0f) ? wn1 : w1;                                          \
        if (RENORM) { w0 *= sc0; E0 += k0; w1 *= sc1; E1 += k1; }              \
        sw[((u)+1)&1][widx][0][lane] = w0;                                     \
        sw[((u)+1)&1][widx][1][lane] = w1;                                     \
        if (RENORM) { scale_from_max(w0, sc0, k0); scale_from_max(w1, sc1, k1); } \
    }

__global__ void __launch_bounds__(64) crf_kernel(
    const float* __restrict__ em,
    const int*   __restrict__ tags,
    const float* __restrict__ mask,
    const float* __restrict__ trans,
    const float* __restrict__ startT,
    const float* __restrict__ endT,
    float*       __restrict__ out)
{
    const int widx = threadIdx.x >> 5;          // 0..1 -> SMSP 0/1 (private)
    const int lane = threadIdx.x & 31;
    const int wg   = blockIdx.x * 2 + widx;     // 128 blocks x 2 warps = 256
    const int b0   = wg * 2;                    // 2 batches per warp
    const int b1   = b0 + 1;

    __shared__ __align__(16) float sw[2][2][2][32];  // [parity][warp][batch][lane]
    __shared__ float red[64];
    __shared__ unsigned s_ticket;

    // lane j holds column j of exp(transitions), shared by both batches
    float et[T_SZ];
#pragma unroll
    for (int i = 0; i < T_SZ; ++i)
        et[i] = __expf(__ldg(trans + i * T_SZ + lane));

    const float* emb0 = em + (size_t)b0 * S_SZ * T_SZ;
    const float* emb1 = em + (size_t)b1 * S_SZ * T_SZ;
    const float* mb0  = mask + (size_t)b0 * S_SZ;
    const float* mb1  = mask + (size_t)b1 * S_SZ;

    // exp-domain state: alpha_j = log(w_j) + E*ln2
    const float stv = __ldg(startT + lane);
    float w0 = __expf(stv + __ldg(emb0 + lane));
    float w1 = __expf(stv + __ldg(emb1 + lane));
    int E0 = 0, E1 = 0;

    sw[0][widx][0][lane] = w0;
    sw[0][widx][1][lane] = w1;

    // pending renorm scale (applied 4 steps from now)
    float sc0, sc1; int k0, k1;
    scale_from_max(w0, sc0, k0);
    scale_from_max(w1, sc1, k1);

    // depth-8 prefetch ring: exp(emission) computed 8 steps ahead of use
    float ee0[8], ee1[8], mk0[8], mk1[8];
#pragma unroll
    for (int k = 0; k < 8; ++k) {
        ee0[k] = __expf(__ldg(emb0 + (1 + k) * T_SZ + lane));
        ee1[k] = __expf(__ldg(emb1 + (1 + k) * T_SZ + lane));
        mk0[k] = __ldg(mb0 + 1 + k);
        mk1[k] = __ldg(mb1 + 1 + k);
    }

    const float4* rd0a = (const float4*)sw[0][widx][0];
    const float4* rd0b = (const float4*)sw[1][widx][0];
    const float4* rd1a = (const float4*)sw[0][widx][1];
    const float4* rd1b = (const float4*)sw[1][widx][1];

    // main loop: steps 1..1016 as 127 groups of 8 (compile-time slots/parity)
    for (int g = 0; g < 127; ++g) {
        const int sb = 1 + g * 8;
        const bool pfl = (g < 126);   // last group: slot 7 would fetch s=1024
        STEP(0, true, false, sb + 0)
        STEP(1, true, false, sb + 1)
        STEP(2, true, false, sb + 2)
        STEP(3, true, true,  sb + 3)
        STEP(4, true, false, sb + 4)
        STEP(5, true, false, sb + 5)
        STEP(6, true, false, sb + 6)
        STEP(7, pfl,  true,  sb + 7)
    }
    // tail: steps 1017..1023 (slots 0..6), no prefetch, one renorm mid-tail
    STEP(0, false, false, 1017)
    STEP(1, false, false, 1018)
    STEP(2, false, false, 1019)
    STEP(3, false, true,  1020)
    STEP(4, false, false, 1021)
    STEP(5, false, false, 1022)
    STEP(6, false, false, 1023)

    // ---- partition = E*ln2 + log( sum_j w_j * exp(endT_j) ) ----
    const float ve = __expf(__ldg(endT + lane));
    float v0 = w0 * ve;
    float v1 = w1 * ve;
#pragma unroll
    for (int o = 16; o > 0; o >>= 1) {
        v0 += __shfl_xor_sync(FULL, v0, o);
        v1 += __shfl_xor_sync(FULL, v1, o);
    }
    const float part0 = fmaf((float)E0, LN2F, __logf(v0));
    const float part1 = fmaf((float)E1, LN2F, __logf(v1));

    // ---- scores: lanes stride over positions, both batches interleaved ----
    const int* tb0 = tags + (size_t)b0 * S_SZ;
    const int* tb1 = tags + (size_t)b1 * S_SZ;
    float sa0 = 0.f, sa1 = 0.f, ms0 = 0.f, ms1 = 0.f;
#pragma unroll 4
    for (int s = lane; s < S_SZ; s += 32) {
        const float mA = __ldg(mb0 + s);
        const float mB = __ldg(mb1 + s);
        ms0 += mA; ms1 += mB;
        if (s == 0) {
            const int tA = __ldg(tb0) & (T_SZ - 1);
            const int tB = __ldg(tb1) & (T_SZ - 1);
            sa0 += __ldg(startT + tA) + __ldg(emb0 + tA);
            sa1 += __ldg(startT + tB) + __ldg(emb1 + tB);
        } else {
            const int cA = __ldg(tb0 + s)     & (T_SZ - 1);
            const int pA = __ldg(tb0 + s - 1) & (T_SZ - 1);
            const int cB = __ldg(tb1 + s)     & (T_SZ - 1);
            const int pB = __ldg(tb1 + s - 1) & (T_SZ - 1);
            sa0 += (__ldg(emb0 + s * T_SZ + cA) + __ldg(trans + pA * T_SZ + cA)) * mA;
            sa1 += (__ldg(emb1 + s * T_SZ + cB) + __ldg(trans + pB * T_SZ + cB)) * mB;
        }
    }
#pragma unroll
    for (int o = 16; o > 0; o >>= 1) {
        sa0 += __shfl_xor_sync(FULL, sa0, o);
        sa1 += __shfl_xor_sync(FULL, sa1, o);
        ms0 += __shfl_xor_sync(FULL, ms0, o);
        ms1 += __shfl_xor_sync(FULL, ms1, o);
    }

    if (lane == 0) {
        int l0 = (int)ms0 - 1; l0 = l0 < 0 ? 0 : (l0 >= S_SZ ? S_SZ - 1 : l0);
        int l1 = (int)ms1 - 1; l1 = l1 < 0 ? 0 : (l1 >= S_SZ ? S_SZ - 1 : l1);
        const int tL0 = __ldg(tb0 + l0) & (T_SZ - 1);
        const int tL1 = __ldg(tb1 + l1) & (T_SZ - 1);
        g_res[b0] = part0 - (sa0 + __ldg(endT + tL0));
        g_res[b1] = part1 - (sa1 + __ldg(endT + tL1));
    }

    // ---- fused final reduction: last block to finish sums all 512 ----
    __syncthreads();
    __threadfence();
    if (threadIdx.x == 0)
        s_ticket = atomicAdd(&g_cnt, 1u);
    __syncthreads();

    if (s_ticket == gridDim.x - 1) {
        const int t = threadIdx.x;
        float acc = 0.f;
#pragma unroll
        for (int r = 0; r < 8; ++r)
            acc += g_res[t + 64 * r];
        red[t] = acc;
        __syncthreads();
#pragma unroll
        for (int st = 32; st > 0; st >>= 1) {
            if (t < st) red[t] += red[t + st];
            __syncthreads();
        }
        if (t == 0) { out[0] = red[0]; g_cnt = 0; }
    }
}

extern "C" void kernel_launch(void* const* d_in, const int* in_sizes, int n_in,
                              void* d_out, int out_size)
{
    const float* em     = (const float*)d_in[0];
    const int*   tags   = (const int*)d_in[1];
    const float* mask   = (const float*)d_in[2];
    const float* trans  = (const float*)d_in[3];
    const float* startT = (const float*)d_in[4];
    const float* endT   = (const float*)d_in[5];
    float* out = (float*)d_out;

    (void)in_sizes; (void)n_in; (void)out_size;

    // 128 blocks x 64 threads = 256 warps, 2 batches per warp,
    // each warp on a private SMSP of its own SM (SMSP 0/1 of 128 SMs)
    crf_kernel<<<128, 64>>>(em, tags, mask, trans, startT, endT, out);
}

// round 14
// speedup vs baseline: 1.7196x; 1.7196x over previous
#include <cuda_runtime.h>
#include <cstddef>

// CRF NLL: emissions (B,S,T) f32, tags (B,S) int32-staged, mask (B,S) f32,
// transitions (T,T) f32, start_transitions (T) f32, end_transitions (T) f32
// out: scalar f32 = sum_b (partition_b - score_b)
#define B_SZ 512
#define S_SZ 1024
#define T_SZ 32
#define FULL 0xFFFFFFFFu
#define LN2F 0.69314718055994530942f

__device__ float    g_res[B_SZ];
__device__ unsigned g_cnt;   // zero-init; reset by last block each launch

// ld.shared.v4 with literal immediate offset; volatile + memory clobber pins
// ordering against the preceding st.shared (no __syncwarp: intra-warp LSU is
// in-order and the stream is divergence-free between STS and LDS).
#define LDS4(x0, x1, x2, x3, base, OFF)                                   \
    asm volatile("ld.shared.v4.f32 {%0,%1,%2,%3}, [%4+" OFF "];"          \
                 : "=f"(x0), "=f"(x1), "=f"(x2), "=f"(x3)                 \
                 : "r"(base) : "memory");

#define STSF(addr, v)                                                     \
    asm volatile("st.shared.f32 [%0], %1;" :: "r"(addr), "f"(v) : "memory");

// One recursion step, pure exp domain. RB = read base (u&1 buffer),
// WA = write address ((u+1)&1 buffer). RENORM applies the exact 2^-k scale
// computed 4 steps ago, then derives the next one from lane 0 (1 SHFL,
// lag-4 pipelined -> off the critical path).
#define STEP(u, RB, WA, PREFETCH, RENORM, s_)                                  \
    {                                                                          \
        const float ee = eebuf[u];                                             \
        const float m  = mbuf[u];                                              \
        if (PREFETCH) {                                                        \
            eebuf[u] = __expf(__ldg(emb + (size_t)((s_) + 8) * T_SZ + lane));  \
            mbuf[u]  = __ldg(mb + ((s_) + 8));                                 \
        }                                                                      \
        float W0,W1,W2,W3,W4,W5,W6,W7,W8,W9,Wa,Wb,Wc,Wd,We,Wf;                 \
        float X0,X1,X2,X3,X4,X5,X6,X7,X8,X9,Xa,Xb,Xc,Xd,Xe,Xf;                 \
        LDS4(W0,W1,W2,W3, RB, "0")                                             \
        LDS4(W4,W5,W6,W7, RB, "16")                                            \
        LDS4(W8,W9,Wa,Wb, RB, "32")                                            \
        LDS4(Wc,Wd,We,Wf, RB, "48")                                            \
        LDS4(X0,X1,X2,X3, RB, "64")                                            \
        LDS4(X4,X5,X6,X7, RB, "80")                                            \
        LDS4(X8,X9,Xa,Xb, RB, "96")                                            \
        LDS4(Xc,Xd,Xe,Xf, RB, "112")                                           \
        float a0 = W0 * et[0];                                                 \
        float a1 = W4 * et[4];                                                 \
        float a2 = W8 * et[8];                                                 \
        float a3 = Wc * et[12];                                                \
        float a4 = X0 * et[16];                                                \
        float a5 = X4 * et[20];                                                \
        float a6 = X8 * et[24];                                                \
        float a7 = Xc * et[28];                                                \
        a0 = fmaf(W1, et[1],  a0);  a1 = fmaf(W5, et[5],  a1);                 \
        a2 = fmaf(W9, et[9],  a2);  a3 = fmaf(Wd, et[13], a3);                 \
        a4 = fmaf(X1, et[17], a4);  a5 = fmaf(X5, et[21], a5);                 \
        a6 = fmaf(X9, et[25], a6);  a7 = fmaf(Xd, et[29], a7);                 \
        a0 = fmaf(W2, et[2],  a0);  a1 = fmaf(W6, et[6],  a1);                 \
        a2 = fmaf(Wa, et[10], a2);  a3 = fmaf(We, et[14], a3);                 \
        a4 = fmaf(X2, et[18], a4);  a5 = fmaf(X6, et[22], a5);                 \
        a6 = fmaf(Xa, et[26], a6);  a7 = fmaf(Xe, et[30], a7);                 \
        a0 = fmaf(W3, et[3],  a0);  a1 = fmaf(W7, et[7],  a1);                 \
        a2 = fmaf(Wb, et[11], a2);  a3 = fmaf(Wf, et[15], a3);                 \
        a4 = fmaf(X3, et[19], a4);  a5 = fmaf(X7, et[23], a5);                 \
        a6 = fmaf(Xb, et[27], a6);  a7 = fmaf(Xf, et[31], a7);                 \
        const float dot = ((a0 + a1) + (a2 + a3)) + ((a4 + a5) + (a6 + a7));   \
        const float wn  = dot * ee;                                            \
        w = fmaf(m, wn - w, w);     /* mask blend: exact for m in {0,1} */     \
        if (RENORM) { w *= sc_a; E += k_a; }                                   \
        STSF(WA, w)                                                            \
        if (RENORM) {                                                          \
            const float w0l = __shfl_sync(FULL, w, 0);                         \
            const int   eb  = (int)((__float_as_uint(w0l) >> 23) & 0xFF);      \
            sc_a = __uint_as_float((unsigned)(254 - eb) << 23);                \
            k_a  = eb - 127;                                                   \
        }                                                                      \
    }

__global__ void __launch_bounds__(128) crf_kernel(
    const float* __restrict__ em,
    const int*   __restrict__ tags,
    const float* __restrict__ mask,
    const float* __restrict__ trans,
    const float* __restrict__ startT,
    const float* __restrict__ endT,
    float*       __restrict__ out)
{
    const int widx = threadIdx.x >> 5;
    const int lane = threadIdx.x & 31;
    const int b    = blockIdx.x * 4 + widx;   // 128 blocks x 4 warps = 512

    __shared__ __align__(16) float sw[2][4][32];  // [parity][warp][lane]
    __shared__ float red[128];
    __shared__ unsigned s_ticket;

    // lane j holds column j of exp(transitions): et[i] = expT[i][j]
    float et[T_SZ];
#pragma unroll
    for (int i = 0; i < T_SZ; ++i)
        et[i] = __expf(__ldg(trans + i * T_SZ + lane));

    const float* emb = em   + (size_t)b * S_SZ * T_SZ;
    const float* mb  = mask + (size_t)b * S_SZ;

    // exp-domain state: alpha_j = log(w_j) + E*ln2   (E warp-uniform)
    float w = __expf(__ldg(startT + lane) + __ldg(emb + lane));
    int   E = 0;

    // smem addresses (u32): read bases per parity, write addrs per parity
    const unsigned sb  = (unsigned)__cvta_generic_to_shared(&sw[0][widx][0]);
    const unsigned ra0 = sb;                // parity-0 buffer base
    const unsigned ra1 = sb + 512;          // parity-1 buffer base
    const unsigned wa0 = sb + lane * 4;     // this lane's slot, parity 0
    const unsigned wa1 = wa0 + 512;         // this lane's slot, parity 1

    STSF(wa0, w)   // prime parity-0 buffer (read by step 1)

    // lag-4 renorm scale from lane 0 (applied at the next renorm point)
    float sc_a; int k_a;
    {
        const float w0l = __shfl_sync(FULL, w, 0);
        const int   eb  = (int)((__float_as_uint(w0l) >> 23) & 0xFF);
        sc_a = __uint_as_float((unsigned)(254 - eb) << 23);   // 2^(127-eb)
        k_a  = eb - 127;
    }

    // depth-8 prefetch ring: exp(emission) computed 8 steps ahead of use
    float eebuf[8], mbuf[8];
#pragma unroll
    for (int k = 0; k < 8; ++k) {
        eebuf[k] = __expf(__ldg(emb + (1 + k) * T_SZ + lane));
        mbuf[k]  = __ldg(mb + 1 + k);
    }

    // main loop: steps 1..1016 as 127 groups of 8 (compile-time slots/parity)
    for (int g = 0; g < 127; ++g) {
        const int sb_ = 1 + g * 8;
        const bool pfl = (g < 126);   // last group: slot 7 would fetch s=1024
        STEP(0, ra0, wa1, true, false, sb_ + 0)
        STEP(1, ra1, wa0, true, false, sb_ + 1)
        STEP(2, ra0, wa1, true, false, sb_ + 2)
        STEP(3, ra1, wa0, true, true,  sb_ + 3)
        STEP(4, ra0, wa1, true, false, sb_ + 4)
        STEP(5, ra1, wa0, true, false, sb_ + 5)
        STEP(6, ra0, wa1, true, false, sb_ + 6)
        STEP(7, ra1, wa0, pfl,  true,  sb_ + 7)
    }
    // tail: steps 1017..1023 (slots 0..6), no prefetch, one renorm mid-tail
    STEP(0, ra0, wa1, false, false, 1017)
    STEP(1, ra1, wa0, false, false, 1018)
    STEP(2, ra0, wa1, false, false, 1019)
    STEP(3, ra1, wa0, false, true,  1020)
    STEP(4, ra0, wa1, false, false, 1021)
    STEP(5, ra1, wa0, false, false, 1022)
    STEP(6, ra0, wa1, false, false, 1023)

    // ---- partition_b = E*ln2 + log( sum_j w_j * exp(endT_j) ) ----
    float v = w * __expf(__ldg(endT + lane));
#pragma unroll
    for (int o = 16; o > 0; o >>= 1)
        v += __shfl_xor_sync(FULL, v, o);
    const float part = fmaf((float)E, LN2F, __logf(v));

    // ---- score_b: lanes stride over positions ----
    const int* tb = tags + (size_t)b * S_SZ;
    float sacc = 0.f, msum = 0.f;
#pragma unroll 4
    for (int s = lane; s < S_SZ; s += 32) {
        const float mm = __ldg(mb + s);
        msum += mm;
        if (s == 0) {
            const int t0 = __ldg(tb) & (T_SZ - 1);
            sacc += __ldg(startT + t0) + __ldg(emb + t0);
        } else {
            const int tc = __ldg(tb + s)     & (T_SZ - 1);
            const int tp = __ldg(tb + s - 1) & (T_SZ - 1);
            sacc += (__ldg(emb + s * T_SZ + tc) + __ldg(trans + tp * T_SZ + tc)) * mm;
        }
    }
#pragma unroll
    for (int o = 16; o > 0; o >>= 1) {
        sacc += __shfl_xor_sync(FULL, sacc, o);
        msum += __shfl_xor_sync(FULL, msum, o);
    }

    if (lane == 0) {
        int last = (int)msum - 1;
        last = last < 0 ? 0 : (last >= S_SZ ? S_SZ - 1 : last);
        const int tl = __ldg(tb + last) & (T_SZ - 1);
        g_res[b] = part - (sacc + __ldg(endT + tl));
    }

    // ---- fused final reduction: last block to finish sums all 512 ----
    __syncthreads();
    __threadfence();
    if (threadIdx.x == 0)
        s_ticket = atomicAdd(&g_cnt, 1u);
    __syncthreads();

    if (s_ticket == gridDim.x - 1) {
        const int t = threadIdx.x;
        red[t] = g_res[t] + g_res[t + 128] + g_res[t + 256] + g_res[t + 384];
        __syncthreads();
#pragma unroll
        for (int st = 64; st > 0; st >>= 1) {
            if (t < st) red[t] += red[t + st];
            __syncthreads();
        }
        if (t == 0) { out[0] = red[0]; g_cnt = 0; }
    }
}

extern "C" void kernel_launch(void* const* d_in, const int* in_sizes, int n_in,
                              void* d_out, int out_size)
{
    const float* em     = (const float*)d_in[0];
    const int*   tags   = (const int*)d_in[1];
    const float* mask   = (const float*)d_in[2];
    const float* trans  = (const float*)d_in[3];
    const float* startT = (const float*)d_in[4];
    const float* endT   = (const float*)d_in[5];
    float* out = (float*)d_out;

    (void)in_sizes; (void)n_in; (void)out_size;

    // 128 blocks x 128 threads = 512 warps = one warp per batch
    crf_kernel<<<B_SZ / 4, 128>>>(em, tags, mask, trans, startT, endT, out);
}

// round 15
// speedup vs baseline: 1.8865x; 1.0970x over previous
#include <cuda_runtime.h>
#include <cstddef>

// CRF NLL: emissions (B,S,T) f32, tags (B,S) int32-staged, mask (B,S) f32,
// transitions (T,T) f32, start_transitions (T) f32, end_transitions (T) f32
// out: scalar f32 = sum_b (partition_b - score_b)
#define B_SZ 512
#define S_SZ 1024
#define T_SZ 32
#define FULL 0xFFFFFFFFu
#define LN2F 0.69314718055994530942f

typedef unsigned long long ull;

__device__ float    g_res[B_SZ];
__device__ unsigned g_cnt;   // zero-init; reset by last block each launch

// ---- packed f32x2 helpers (PTX-only; ptxas never auto-fuses) ----
__device__ __forceinline__ ull ffma2(ull a, ull b, ull c) {
    ull d; asm("fma.rn.f32x2 %0, %1, %2, %3;" : "=l"(d) : "l"(a), "l"(b), "l"(c));
    return d;
}
__device__ __forceinline__ ull fmul2(ull a, ull b) {
    ull d; asm("mul.rn.f32x2 %0, %1, %2;" : "=l"(d) : "l"(a), "l"(b));
    return d;
}
__device__ __forceinline__ ull fadd2(ull a, ull b) {
    ull d; asm("add.rn.f32x2 %0, %1, %2;" : "=l"(d) : "l"(a), "l"(b));
    return d;
}
__device__ __forceinline__ ull pack2(float lo, float hi) {
    ull d; asm("mov.b64 %0, {%1, %2};" : "=l"(d) : "f"(lo), "f"(hi));
    return d;
}
__device__ __forceinline__ float hadd2(ull v) {
    float lo, hi;
    asm("mov.b64 {%0, %1}, %2;" : "=f"(lo), "=f"(hi) : "l"(v));
    return lo + hi;
}

// ld.shared.v2.u64: two even-aligned 64-bit float pairs per 16B load.
// volatile + memory clobber pins ordering vs the preceding st.shared
// (no __syncwarp: intra-warp LSU is in-order, stream is divergence-free).
#define LDSU2(x0, x1, base, OFF)                                          \
    asm volatile("ld.shared.v2.u64 {%0,%1}, [%2+" OFF "];"                \
                 : "=l"(x0), "=l"(x1) : "r"(base) : "memory");

#define STSF(addr, v)                                                     \
    asm volatile("st.shared.f32 [%0], %1;" :: "r"(addr), "f"(v) : "memory");

// One recursion step, pure exp domain, f32x2 dot (19 fma-class ops).
// RB = read base (u&1 buffer), WA = write address ((u+1)&1 buffer).
// RENORM applies the exact 2^-k scale computed 4 steps ago, then derives
// the next one from lane 0 (1 SHFL, lag-4 pipelined -> off critical path).
#define STEP(u, RB, WA, PREFETCH, RENORM, s_)                                  \
    {                                                                          \
        const float ee = eebuf[u];                                             \
        const float m  = mbuf[u];                                              \
        if (PREFETCH) {                                                        \
            eebuf[u] = __expf(__ldg(emb + (size_t)((s_) + 8) * T_SZ + lane));  \
            mbuf[u]  = __ldg(mb + ((s_) + 8));                                 \
        }                                                                      \
        ull P0,P1,P2,P3,P4,P5,P6,P7,P8,P9,Pa,Pb,Pc,Pd,Pe,Pf;                   \
        LDSU2(P0, P1, RB, "0")                                                 \
        LDSU2(P2, P3, RB, "16")                                                \
        LDSU2(P4, P5, RB, "32")                                                \
        LDSU2(P6, P7, RB, "48")                                                \
        LDSU2(P8, P9, RB, "64")                                                \
        LDSU2(Pa, Pb, RB, "80")                                                \
        LDSU2(Pc, Pd, RB, "96")                                                \
        LDSU2(Pe, Pf, RB, "112")                                               \
        ull q0 = fmul2(P0, et2[0]);                                            \
        ull q1 = fmul2(P1, et2[1]);                                            \
        ull q2 = fmul2(P2, et2[2]);                                            \
        ull q3 = fmul2(P3, et2[3]);                                            \
        q0 = ffma2(P4, et2[4],  q0);                                           \
        q1 = ffma2(P5, et2[5],  q1);                                           \
        q2 = ffma2(P6, et2[6],  q2);                                           \
        q3 = ffma2(P7, et2[7],  q3);                                           \
        q0 = ffma2(P8, et2[8],  q0);                                           \
        q1 = ffma2(P9, et2[9],  q1);                                           \
        q2 = ffma2(Pa, et2[10], q2);                                           \
        q3 = ffma2(Pb, et2[11], q3);                                           \
        q0 = ffma2(Pc, et2[12], q0);                                           \
        q1 = ffma2(Pd, et2[13], q1);                                           \
        q2 = ffma2(Pe, et2[14], q2);                                           \
        q3 = ffma2(Pf, et2[15], q3);                                           \
        const float dot = hadd2(fadd2(fadd2(q0, q1), fadd2(q2, q3)));          \
        const float wn  = dot * ee;                                            \
        w = fmaf(m, wn - w, w);     /* mask blend: exact for m in {0,1} */     \
        if (RENORM) { w *= sc_a; E += k_a; }                                   \
        STSF(WA, w)                                                            \
        if (RENORM) {                                                          \
            const float w0l = __shfl_sync(FULL, w, 0);                         \
            const int   eb  = (int)((__float_as_uint(w0l) >> 23) & 0xFF);      \
            sc_a = __uint_as_float((unsigned)(254 - eb) << 23);                \
            k_a  = eb - 127;                                                   \
        }                                                                      \
    }

__global__ void __launch_bounds__(128) crf_kernel(
    const float* __restrict__ em,
    const int*   __restrict__ tags,
    const float* __restrict__ mask,
    const float* __restrict__ trans,
    const float* __restrict__ startT,
    const float* __restrict__ endT,
    float*       __restrict__ out)
{
    const int widx = threadIdx.x >> 5;
    const int lane = threadIdx.x & 31;
    const int b    = blockIdx.x * 4 + widx;   // 128 blocks x 4 warps = 512

    __shared__ __align__(16) float sw[2][4][32];  // [parity][warp][lane]
    __shared__ float red[128];
    __shared__ unsigned s_ticket;

    // lane j holds column j of exp(transitions), packed in pairs along i:
    // et2[k] = ( expT[2k][lane], expT[2k+1][lane] )
    ull et2[T_SZ / 2];
#pragma unroll
    for (int k = 0; k < T_SZ / 2; ++k) {
        const float a = __expf(__ldg(trans + (2 * k)     * T_SZ + lane));
        const float c = __expf(__ldg(trans + (2 * k + 1) * T_SZ + lane));
        et2[k] = pack2(a, c);
    }

    const float* emb = em   + (size_t)b * S_SZ * T_SZ;
    const float* mb  = mask + (size_t)b * S_SZ;

    // exp-domain state: alpha_j = log(w_j) + E*ln2   (E warp-uniform)
    float w = __expf(__ldg(startT + lane) + __ldg(emb + lane));
    int   E = 0;

    // smem addresses (u32): read bases per parity, write addrs per parity
    const unsigned sb  = (unsigned)__cvta_generic_to_shared(&sw[0][widx][0]);
    const unsigned ra0 = sb;                // parity-0 buffer base
    const unsigned ra1 = sb + 512;          // parity-1 buffer base
    const unsigned wa0 = sb + lane * 4;     // this lane's slot, parity 0
    const unsigned wa1 = wa0 + 512;         // this lane's slot, parity 1

    STSF(wa0, w)   // prime parity-0 buffer (read by step 1)

    // lag-4 renorm scale from lane 0 (applied at the next renorm point)
    float sc_a; int k_a;
    {
        const float w0l = __shfl_sync(FULL, w, 0);
        const int   eb  = (int)((__float_as_uint(w0l) >> 23) & 0xFF);
        sc_a = __uint_as_float((unsigned)(254 - eb) << 23);   // 2^(127-eb)
        k_a  = eb - 127;
    }

    // depth-8 prefetch ring: exp(emission) computed 8 steps ahead of use
    float eebuf[8], mbuf[8];
#pragma unroll
    for (int k = 0; k < 8; ++k) {
        eebuf[k] = __expf(__ldg(emb + (1 + k) * T_SZ + lane));
        mbuf[k]  = __ldg(mb + 1 + k);
    }

    // main loop: steps 1..1016 as 127 groups of 8 (compile-time slots/parity)
    for (int g = 0; g < 127; ++g) {
        const int sbase = 1 + g * 8;
        const bool pfl = (g < 126);   // last group: slot 7 would fetch s=1024
        STEP(0, ra0, wa1, true, false, sbase + 0)
        STEP(1, ra1, wa0, true, false, sbase + 1)
        STEP(2, ra0, wa1, true, false, sbase + 2)
        STEP(3, ra1, wa0, true, true,  sbase + 3)
        STEP(4, ra0, wa1, true, false, sbase + 4)
        STEP(5, ra1, wa0, true, false, sbase + 5)
        STEP(6, ra0, wa1, true, false, sbase + 6)
        STEP(7, ra1, wa0, pfl,  true,  sbase + 7)
    }
    // tail: steps 1017..1023 (slots 0..6), no prefetch, one renorm mid-tail
    STEP(0, ra0, wa1, false, false, 1017)
    STEP(1, ra1, wa0, false, false, 1018)
    STEP(2, ra0, wa1, false, false, 1019)
    STEP(3, ra1, wa0, false, true,  1020)
    STEP(4, ra0, wa1, false, false, 1021)
    STEP(5, ra1, wa0, false, false, 1022)
    STEP(6, ra0, wa1, false, false, 1023)

    // ---- partition_b = E*ln2 + log( sum_j w_j * exp(endT_j) ) ----
    float v = w * __expf(__ldg(endT + lane));
#pragma unroll
    for (int o = 16; o > 0; o >>= 1)
        v += __shfl_xor_sync(FULL, v, o);
    const float part = fmaf((float)E, LN2F, __logf(v));

    // ---- score_b: lanes stride over positions ----
    const int* tb = tags + (size_t)b * S_SZ;
    float sacc = 0.f, msum = 0.f;
#pragma unroll 4
    for (int s = lane; s < S_SZ; s += 32) {
        const float mm = __ldg(mb + s);
        msum += mm;
        if (s == 0) {
            const int t0 = __ldg(tb) & (T_SZ - 1);
            sacc += __ldg(startT + t0) + __ldg(emb + t0);
        } else {
            const int tc = __ldg(tb + s)     & (T_SZ - 1);
            const int tp = __ldg(tb + s - 1) & (T_SZ - 1);
            sacc += (__ldg(emb + s * T_SZ + tc) + __ldg(trans + tp * T_SZ + tc)) * mm;
        }
    }
#pragma unroll
    for (int o = 16; o > 0; o >>= 1) {
        sacc += __shfl_xor_sync(FULL, sacc, o);
        msum += __shfl_xor_sync(FULL, msum, o);
    }

    if (lane == 0) {
        int last = (int)msum - 1;
        last = last < 0 ? 0 : (last >= S_SZ ? S_SZ - 1 : last);
        const int tl = __ldg(tb + last) & (T_SZ - 1);
        g_res[b] = part - (sacc + __ldg(endT + tl));
    }

    // ---- fused final reduction: last block to finish sums all 512 ----
    __syncthreads();
    __threadfence();
    if (threadIdx.x == 0)
        s_ticket = atomicAdd(&g_cnt, 1u);
    __syncthreads();

    if (s_ticket == gridDim.x - 1) {
        const int t = threadIdx.x;
        red[t] = g_res[t] + g_res[t + 128] + g_res[t + 256] + g_res[t + 384];
        __syncthreads();
#pragma unroll
        for (int st = 64; st > 0; st >>= 1) {
            if (t < st) red[t] += red[t + st];
            __syncthreads();
        }
        if (t == 0) { out[0] = red[0]; g_cnt = 0; }
    }
}

extern "C" void kernel_launch(void* const* d_in, const int* in_sizes, int n_in,
                              void* d_out, int out_size)
{
    const float* em     = (const float*)d_in[0];
    const int*   tags   = (const int*)d_in[1];
    const float* mask   = (const float*)d_in[2];
    const float* trans  = (const float*)d_in[3];
    const float* startT = (const float*)d_in[4];
    const float* endT   = (const float*)d_in[5];
    float* out = (float*)d_out;

    (void)in_sizes; (void)n_in; (void)out_size;

    // 128 blocks x 128 threads = 512 warps = one warp per batch
    crf_kernel<<<B_SZ / 4, 128>>>(em, tags, mask, trans, startT, endT, out);
}

// round 16
// speedup vs baseline: 2.1668x; 1.1486x over previous
#include <cuda_runtime.h>
#include <cstddef>

// CRF NLL via meet-in-the-middle: forward to s=512, backward from s=1023,
// combine Z = sum_i alpha_512[i] * beta_512[i]. Two independent 512-step
// chains per warp hide each other's STS->LDS round-trip latency.
#define B_SZ 512
#define S_SZ 1024
#define T_SZ 32
#define FULL 0xFFFFFFFFu
#define LN2F 0.69314718055994530942f

typedef unsigned long long ull;

__device__ float    g_res[B_SZ];
__device__ unsigned g_cnt;   // zero-init; reset by last block each launch

// ---- packed f32x2 helpers (PTX-only; ptxas never auto-fuses) ----
__device__ __forceinline__ ull ffma2(ull a, ull b, ull c) {
    ull d; asm("fma.rn.f32x2 %0, %1, %2, %3;" : "=l"(d) : "l"(a), "l"(b), "l"(c));
    return d;
}
__device__ __forceinline__ ull fmul2(ull a, ull b) {
    ull d; asm("mul.rn.f32x2 %0, %1, %2;" : "=l"(d) : "l"(a), "l"(b));
    return d;
}
__device__ __forceinline__ ull fadd2(ull a, ull b) {
    ull d; asm("add.rn.f32x2 %0, %1, %2;" : "=l"(d) : "l"(a), "l"(b));
    return d;
}
__device__ __forceinline__ ull pack2(float lo, float hi) {
    ull d; asm("mov.b64 %0, {%1, %2};" : "=l"(d) : "f"(lo), "f"(hi));
    return d;
}
__device__ __forceinline__ float hadd2(ull v) {
    float lo, hi;
    asm("mov.b64 {%0, %1}, %2;" : "=f"(lo), "=f"(hi) : "l"(v));
    return lo + hi;
}

#define LDSU2(x0, x1, base, OFF)                                          \
    asm volatile("ld.shared.v2.u64 {%0,%1}, [%2+" OFF "];"                \
                 : "=l"(x0), "=l"(x1) : "r"(base) : "memory");

#define STSF(addr, v)                                                     \
    asm volatile("st.shared.f32 [%0], %1;" :: "r"(addr), "f"(v) : "memory");

// 16-load dot against a register-resident packed matrix
#define DOT16(RES, RB, MAT)                                               \
    {                                                                      \
        ull Q0,Q1,Q2,Q3,Q4,Q5,Q6,Q7,Q8,Q9,Qa,Qb,Qc,Qd,Qe,Qf;              \
        LDSU2(Q0, Q1, RB, "0")                                             \
        LDSU2(Q2, Q3, RB, "16")                                            \
        LDSU2(Q4, Q5, RB, "32")                                            \
        LDSU2(Q6, Q7, RB, "48")                                            \
        LDSU2(Q8, Q9, RB, "64")                                            \
        LDSU2(Qa, Qb, RB, "80")                                            \
        LDSU2(Qc, Qd, RB, "96")                                            \
        LDSU2(Qe, Qf, RB, "112")                                           \
        ull r0 = fmul2(Q0, MAT[0]);                                        \
        ull r1 = fmul2(Q1, MAT[1]);                                        \
        ull r2 = fmul2(Q2, MAT[2]);                                        \
        ull r3 = fmul2(Q3, MAT[3]);                                        \
        r0 = ffma2(Q4, MAT[4],  r0);                                       \
        r1 = ffma2(Q5, MAT[5],  r1);                                       \
        r2 = ffma2(Q6, MAT[6],  r2);                                       \
        r3 = ffma2(Q7, MAT[7],  r3);                                       \
        r0 = ffma2(Q8, MAT[8],  r0);                                       \
        r1 = ffma2(Q9, MAT[9],  r1);                                       \
        r2 = ffma2(Qa, MAT[10], r2);                                       \
        r3 = ffma2(Qb, MAT[11], r3);                                       \
        r0 = ffma2(Qc, MAT[12], r0);                                       \
        r1 = ffma2(Qd, MAT[13], r1);                                       \
        r2 = ffma2(Qe, MAT[14], r2);                                       \
        r3 = ffma2(Qf, MAT[15], r3);                                       \
        RES = hadd2(fadd2(fadd2(r0, r1), fadd2(r2, r3)));                  \
    }

// Forward step s: reads w vector, w_new = blend(m_s, dot*ee_s, w)
#define STEPF(u, RB, WA, PF, RN, s_)                                           \
    {                                                                          \
        const float ee = eef[u];                                               \
        const float m  = mkf[u];                                               \
        if (PF) {                                                              \
            eef[u] = __expf(__ldg(emb + (size_t)((s_) + 8) * T_SZ + lane));    \
            mkf[u] = __ldg(mb + ((s_) + 8));                                   \
        }                                                                      \
        float dotf;                                                            \
        DOT16(dotf, RB, et2)                                                   \
        const float wn = dotf * ee;                                            \
        wf = fmaf(m, wn - wf, wf);                                             \
        if (RN) { wf *= scf; Ef += kf; }                                       \
        STSF(WA, wf)                                                           \
        if (RN) {                                                              \
            const float w0l = __shfl_sync(FULL, wf, 0);                        \
            const int   eb_ = (int)((__float_as_uint(w0l) >> 23) & 0xFF);      \
            scf = __uint_as_float((unsigned)(254 - eb_) << 23);                \
            kf  = eb_ - 127;                                                   \
        }                                                                      \
    }

// Backward step t: reads x = ee_t*beta_t vector, beta_{t-1} = blend(m_t, dot, beta_t),
// stores x' = beta_{t-1} * ee_{t-1}
#define STEPB(u, RB, WA, PF, RN, t_)                                           \
    {                                                                          \
        const float eeN = eeb[u];   /* ee_{t-1} */                             \
        const float mT  = mkb[u];   /* m_t      */                             \
        if (PF) {                                                              \
            eeb[u] = __expf(__ldg(emb + (size_t)((t_) - 9) * T_SZ + lane));    \
            mkb[u] = __ldg(mb + ((t_) - 8));                                   \
        }                                                                      \
        float dotb;                                                            \
        DOT16(dotb, RB, etb2)                                                  \
        wb = fmaf(mT, dotb - wb, wb);                                          \
        if (RN) { wb *= scb; Eb += kb; }                                       \
        STSF(WA, wb * eeN)                                                     \
        if (RN) {                                                              \
            const float w0l = __shfl_sync(FULL, wb, 0);                        \
            const int   eb_ = (int)((__float_as_uint(w0l) >> 23) & 0xFF);      \
            scb = __uint_as_float((unsigned)(254 - eb_) << 23);                \
            kb  = eb_ - 127;                                                   \
        }                                                                      \
    }

__global__ void __launch_bounds__(128) crf_kernel(
    const float* __restrict__ em,
    const int*   __restrict__ tags,
    const float* __restrict__ mask,
    const float* __restrict__ trans,
    const float* __restrict__ startT,
    const float* __restrict__ endT,
    float*       __restrict__ out)
{
    const int widx = threadIdx.x >> 5;
    const int lane = threadIdx.x & 31;
    const int b    = blockIdx.x * 4 + widx;   // 128 blocks x 4 warps = 512

    __shared__ __align__(16) float swf[2][4][32];  // forward  [parity][warp][lane]
    __shared__ __align__(16) float swb[2][4][32];  // backward [parity][warp][lane]
    __shared__ float red[128];
    __shared__ unsigned s_ticket;

    // et2 : column 'lane' of expT packed along i  (forward:  dot_j = sum_i w_i expT[i][j])
    // etb2: row    'lane' of expT packed along j  (backward: dot_i = sum_j x_j expT[i][j])
    ull et2[T_SZ / 2], etb2[T_SZ / 2];
#pragma unroll
    for (int k = 0; k < T_SZ / 2; ++k) {
        et2[k]  = pack2(__expf(__ldg(trans + (2 * k)     * T_SZ + lane)),
                        __expf(__ldg(trans + (2 * k + 1) * T_SZ + lane)));
        etb2[k] = pack2(__expf(__ldg(trans + lane * T_SZ + 2 * k)),
                        __expf(__ldg(trans + lane * T_SZ + 2 * k + 1)));
    }

    const float* emb = em   + (size_t)b * S_SZ * T_SZ;
    const float* mb  = mask + (size_t)b * S_SZ;

    // chain states (exp domain with warp-uniform power-of-2 exponents)
    float wf = __expf(__ldg(startT + lane) + __ldg(emb + lane));             // alpha_0
    float wb = __expf(__ldg(endT + lane));                                    // beta_1023
    int Ef = 0, Eb = 0;

    // smem addresses
    const unsigned sbf  = (unsigned)__cvta_generic_to_shared(&swf[0][widx][0]);
    const unsigned sbb  = (unsigned)__cvta_generic_to_shared(&swb[0][widx][0]);
    const unsigned raf0 = sbf,            raf1 = sbf + 512;
    const unsigned rab0 = sbb,            rab1 = sbb + 512;
    const unsigned waf0 = sbf + lane * 4, waf1 = waf0 + 512;
    const unsigned wab0 = sbb + lane * 4, wab1 = wab0 + 512;

    STSF(waf0, wf)                                             // prime fwd: w at s=0
    STSF(wab0, wb * __expf(__ldg(emb + 1023 * T_SZ + lane)))   // prime bwd: x_1023

    // lag-4 renorm scales
    float scf, scb; int kf, kb;
    {
        float w0l = __shfl_sync(FULL, wf, 0);
        int e_ = (int)((__float_as_uint(w0l) >> 23) & 0xFF);
        scf = __uint_as_float((unsigned)(254 - e_) << 23);  kf = e_ - 127;
        w0l = __shfl_sync(FULL, wb, 0);
        e_ = (int)((__float_as_uint(w0l) >> 23) & 0xFF);
        scb = __uint_as_float((unsigned)(254 - e_) << 23);  kb = e_ - 127;
    }

    // depth-8 prefetch rings
    float eef[8], mkf[8], eeb[8], mkb[8];
#pragma unroll
    for (int k = 0; k < 8; ++k) {
        eef[k] = __expf(__ldg(emb + (1 + k) * T_SZ + lane));       // ee_s, s=1..8
        mkf[k] = __ldg(mb + 1 + k);                                // m_s
        eeb[k] = __expf(__ldg(emb + (1022 - k) * T_SZ + lane));    // ee_{t-1}, t=1023-k
        mkb[k] = __ldg(mb + 1023 - k);                             // m_t
    }

    // 63 groups of 8 pairs: fwd s=1..504, bwd t=1023..520
    for (int g = 0; g < 63; ++g) {
        const int sb_ = 1 + g * 8;
        const int tb_ = 1023 - g * 8;
        STEPF(0, raf0, waf1, true, false, sb_ + 0)  STEPB(0, rab0, wab1, true, false, tb_ - 0)
        STEPF(1, raf1, waf0, true, false, sb_ + 1)  STEPB(1, rab1, wab0, true, false, tb_ - 1)
        STEPF(2, raf0, waf1, true, false, sb_ + 2)  STEPB(2, rab0, wab1, true, false, tb_ - 2)
        STEPF(3, raf1, waf0, true, true,  sb_ + 3)  STEPB(3, rab1, wab0, true, true,  tb_ - 3)
        STEPF(4, raf0, waf1, true, false, sb_ + 4)  STEPB(4, rab0, wab1, true, false, tb_ - 4)
        STEPF(5, raf1, waf0, true, false, sb_ + 5)  STEPB(5, rab1, wab0, true, false, tb_ - 5)
        STEPF(6, raf0, waf1, true, false, sb_ + 6)  STEPB(6, rab0, wab1, true, false, tb_ - 6)
        STEPF(7, raf1, waf0, true, true,  sb_ + 7)  STEPB(7, rab1, wab0, true, true,  tb_ - 7)
    }
    // tail: fwd s=505..512 (8 steps), bwd t=519..513 (7 steps)
    STEPF(0, raf0, waf1, false, false, 505)  STEPB(0, rab0, wab1, false, false, 519)
    STEPF(1, raf1, waf0, false, false, 506)  STEPB(1, rab1, wab0, false, false, 518)
    STEPF(2, raf0, waf1, false, false, 507)  STEPB(2, rab0, wab1, false, false, 517)
    STEPF(3, raf1, waf0, false, true,  508)  STEPB(3, rab1, wab0, false, true,  516)
    STEPF(4, raf0, waf1, false, false, 509)  STEPB(4, rab0, wab1, false, false, 515)
    STEPF(5, raf1, waf0, false, false, 510)  STEPB(5, rab1, wab0, false, false, 514)
    STEPF(6, raf0, waf1, false, false, 511)  STEPB(6, rab0, wab1, false, false, 513)
    STEPF(7, raf1, waf0, false, false, 512)

    // ---- partition = (Ef+Eb)*ln2 + log( sum_i alpha_512[i] * beta_512[i] ) ----
    float v = wf * wb;
#pragma unroll
    for (int o = 16; o > 0; o >>= 1)
        v += __shfl_xor_sync(FULL, v, o);
    const float part = fmaf((float)(Ef + Eb), LN2F, __logf(v));

    // ---- score_b: lanes stride over positions ----
    const int* tb = tags + (size_t)b * S_SZ;
    float sacc = 0.f, msum = 0.f;
#pragma unroll 4
    for (int s = lane; s < S_SZ; s += 32) {
        const float mm = __ldg(mb + s);
        msum += mm;
        if (s == 0) {
            const int t0 = __ldg(tb) & (T_SZ - 1);
            sacc += __ldg(startT + t0) + __ldg(emb + t0);
        } else {
            const int tc = __ldg(tb + s)     & (T_SZ - 1);
            const int tp = __ldg(tb + s - 1) & (T_SZ - 1);
            sacc += (__ldg(emb + s * T_SZ + tc) + __ldg(trans + tp * T_SZ + tc)) * mm;
        }
    }
#pragma unroll
    for (int o = 16; o > 0; o >>= 1) {
        sacc += __shfl_xor_sync(FULL, sacc, o);
        msum += __shfl_xor_sync(FULL, msum, o);
    }

    if (lane == 0) {
        int last = (int)msum - 1;
        last = last < 0 ? 0 : (last >= S_SZ ? S_SZ - 1 : last);
        const int tl = __ldg(tb + last) & (T_SZ - 1);
        g_res[b] = part - (sacc + __ldg(endT + tl));
    }

    // ---- fused final reduction: last block to finish sums all 512 ----
    __syncthreads();
    __threadfence();
    if (threadIdx.x == 0)
        s_ticket = atomicAdd(&g_cnt, 1u);
    __syncthreads();

    if (s_ticket == gridDim.x - 1) {
        const int t = threadIdx.x;
        red[t] = g_res[t] + g_res[t + 128] + g_res[t + 256] + g_res[t + 384];
        __syncthreads();
#pragma unroll
        for (int st = 64; st > 0; st >>= 1) {
            if (t < st) red[t] += red[t + st];
            __syncthreads();
        }
        if (t == 0) { out[0] = red[0]; g_cnt = 0; }
    }
}

extern "C" void kernel_launch(void* const* d_in, const int* in_sizes, int n_in,
                              void* d_out, int out_size)
{
    const float* em     = (const float*)d_in[0];
    const int*   tags   = (const int*)d_in[1];
    const float* mask   = (const float*)d_in[2];
    const float* trans  = (const float*)d_in[3];
    const float* startT = (const float*)d_in[4];
    const float* endT   = (const float*)d_in[5];
    float* out = (float*)d_out;

    (void)in_sizes; (void)n_in; (void)out_size;

    // 128 blocks x 128 threads = 512 warps = one warp per batch,
    // each warp runs forward+backward half-chains simultaneously
    crf_kernel<<<B_SZ / 4, 128>>>(em, tags, mask, trans, startT, endT, out);
}

// round 17
// speedup vs baseline: 2.6789x; 1.2363x over previous
#include <cuda_runtime.h>
#include <cstddef>

// CRF NLL, meet-in-the-middle across WARPS: per batch, warp A runs the
// forward chain (alpha: s=1..512), warp B the backward chain (beta:
// t=1023..513); Z = sum_i alpha_512[i]*beta_512[i] combined via smem.
// Each warp runs the lean single-chain step (f32x2 dot, no syncwarp,
// lag-4 exact 2^-k renorm, depth-8 prefetch ring).
#define B_SZ 512
#define S_SZ 1024
#define T_SZ 32
#define FULL 0xFFFFFFFFu
#define LN2F 0.69314718055994530942f

typedef unsigned long long ull;

__device__ float    g_res[B_SZ];
__device__ unsigned g_cnt;   // zero-init; reset by last block each launch

// ---- packed f32x2 helpers (PTX-only; ptxas never auto-fuses) ----
__device__ __forceinline__ ull ffma2(ull a, ull b, ull c) {
    ull d; asm("fma.rn.f32x2 %0, %1, %2, %3;" : "=l"(d) : "l"(a), "l"(b), "l"(c));
    return d;
}
__device__ __forceinline__ ull fmul2(ull a, ull b) {
    ull d; asm("mul.rn.f32x2 %0, %1, %2;" : "=l"(d) : "l"(a), "l"(b));
    return d;
}
__device__ __forceinline__ ull fadd2(ull a, ull b) {
    ull d; asm("add.rn.f32x2 %0, %1, %2;" : "=l"(d) : "l"(a), "l"(b));
    return d;
}
__device__ __forceinline__ ull pack2(float lo, float hi) {
    ull d; asm("mov.b64 %0, {%1, %2};" : "=l"(d) : "f"(lo), "f"(hi));
    return d;
}
__device__ __forceinline__ float hadd2(ull v) {
    float lo, hi;
    asm("mov.b64 {%0, %1}, %2;" : "=f"(lo), "=f"(hi) : "l"(v));
    return lo + hi;
}

#define LDSU2(x0, x1, base, OFF)                                          \
    asm volatile("ld.shared.v2.u64 {%0,%1}, [%2+" OFF "];"                \
                 : "=l"(x0), "=l"(x1) : "r"(base) : "memory");

#define STSF(addr, v)                                                     \
    asm volatile("st.shared.f32 [%0], %1;" :: "r"(addr), "f"(v) : "memory");

// 16-load dot against the register-resident packed matrix mat2
#define DOT16(RES, RB)                                                    \
    {                                                                      \
        ull Q0,Q1,Q2,Q3,Q4,Q5,Q6,Q7,Q8,Q9,Qa,Qb,Qc,Qd,Qe,Qf;              \
        LDSU2(Q0, Q1, RB, "0")                                             \
        LDSU2(Q2, Q3, RB, "16")                                            \
        LDSU2(Q4, Q5, RB, "32")                                            \
        LDSU2(Q6, Q7, RB, "48")                                            \
        LDSU2(Q8, Q9, RB, "64")                                            \
        LDSU2(Qa, Qb, RB, "80")                                            \
        LDSU2(Qc, Qd, RB, "96")                                            \
        LDSU2(Qe, Qf, RB, "112")                                           \
        ull r0 = fmul2(Q0, mat2[0]);                                       \
        ull r1 = fmul2(Q1, mat2[1]);                                       \
        ull r2 = fmul2(Q2, mat2[2]);                                       \
        ull r3 = fmul2(Q3, mat2[3]);                                       \
        r0 = ffma2(Q4, mat2[4],  r0);                                      \
        r1 = ffma2(Q5, mat2[5],  r1);                                      \
        r2 = ffma2(Q6, mat2[6],  r2);                                      \
        r3 = ffma2(Q7, mat2[7],  r3);                                      \
        r0 = ffma2(Q8, mat2[8],  r0);                                      \
        r1 = ffma2(Q9, mat2[9],  r1);                                      \
        r2 = ffma2(Qa, mat2[10], r2);                                      \
        r3 = ffma2(Qb, mat2[11], r3);                                      \
        r0 = ffma2(Qc, mat2[12], r0);                                      \
        r1 = ffma2(Qd, mat2[13], r1);                                      \
        r2 = ffma2(Qe, mat2[14], r2);                                      \
        r3 = ffma2(Qf, mat2[15], r3);                                      \
        RES = hadd2(fadd2(fadd2(r0, r1), fadd2(r2, r3)));                  \
    }

// Forward step s: w_new = blend(m_s, dot*ee_s, w); store w
#define STEPF(u, RB, WA, RN, s_)                                               \
    {                                                                          \
        const float ee = eer[u];                                               \
        const float m  = mkr[u];                                               \
        eer[u] = __expf(__ldg(emb + (size_t)((s_) + 8) * T_SZ + lane));        \
        mkr[u] = __ldg(mb + ((s_) + 8));                                       \
        float dotv;                                                            \
        DOT16(dotv, RB)                                                        \
        const float wn = dotv * ee;                                            \
        w = fmaf(m, wn - w, w);                                                \
        if (RN) { w *= sc_a; E += k_a; }                                       \
        STSF(WA, w)                                                            \
        if (RN) {                                                              \
            const float w0l = __shfl_sync(FULL, w, 0);                         \
            const int   eb_ = (int)((__float_as_uint(w0l) >> 23) & 0xFF);      \
            sc_a = __uint_as_float((unsigned)(254 - eb_) << 23);               \
            k_a  = eb_ - 127;                                                  \
        }                                                                      \
    }

// Backward step t: reads x = ee_t*beta_t, beta_{t-1} = blend(m_t, dot, beta_t);
// store x' = beta_{t-1} * ee_{t-1}
#define STEPB(u, RB, WA, RN, t_)                                               \
    {                                                                          \
        const float eeN = eer[u];   /* ee_{t-1} */                             \
        const float mT  = mkr[u];   /* m_t      */                             \
        eer[u] = __expf(__ldg(emb + (size_t)((t_) - 9) * T_SZ + lane));        \
        mkr[u] = __ldg(mb + ((t_) - 8));                                       \
        float dotv;                                                            \
        DOT16(dotv, RB)                                                        \
        w = fmaf(mT, dotv - w, w);                                             \
        if (RN) { w *= sc_a; E += k_a; }                                       \
        STSF(WA, w * eeN)                                                      \
        if (RN) {                                                              \
            const float w0l = __shfl_sync(FULL, w, 0);                         \
            const int   eb_ = (int)((__float_as_uint(w0l) >> 23) & 0xFF);      \
            sc_a = __uint_as_float((unsigned)(254 - eb_) << 23);               \
            k_a  = eb_ - 127;                                                  \
        }                                                                      \
    }

__global__ void __launch_bounds__(128) crf_kernel(
    const float* __restrict__ em,
    const int*   __restrict__ tags,
    const float* __restrict__ mask,
    const float* __restrict__ trans,
    const float* __restrict__ startT,
    const float* __restrict__ endT,
    float*       __restrict__ out)
{
    const int widx = threadIdx.x >> 5;        // 0..3
    const int lane = threadIdx.x & 31;
    const int pair = widx >> 1;               // batch slot within block (0/1)
    const int role = widx & 1;                // 0 = forward, 1 = backward
    const int b    = blockIdx.x * 2 + pair;   // 256 blocks x 2 batches = 512

    __shared__ __align__(16) float sw[2][4][32];   // ping-pong [parity][warp][lane]
    __shared__ float sxb[2][32];                    // beta_512 per batch slot
    __shared__ int   sEb[2];                        // backward exponent
    __shared__ float ssc[2][2], sms[2][2];          // score partials [pair][role]
    __shared__ float red[128];
    __shared__ unsigned s_ticket;

    // role 0: column 'lane' of expT packed along i (dot_j = sum_i w_i expT[i][j])
    // role 1: row    'lane' of expT packed along j (dot_i = sum_j x_j expT[i][j])
    ull mat2[T_SZ / 2];
    if (role == 0) {
#pragma unroll
        for (int k = 0; k < T_SZ / 2; ++k)
            mat2[k] = pack2(__expf(__ldg(trans + (2 * k)     * T_SZ + lane)),
                            __expf(__ldg(trans + (2 * k + 1) * T_SZ + lane)));
    } else {
#pragma unroll
        for (int k = 0; k < T_SZ / 2; ++k)
            mat2[k] = pack2(__expf(__ldg(trans + lane * T_SZ + 2 * k)),
                            __expf(__ldg(trans + lane * T_SZ + 2 * k + 1)));
    }

    const float* emb = em   + (size_t)b * S_SZ * T_SZ;
    const float* mb  = mask + (size_t)b * S_SZ;

    // chain state (exp domain, warp-uniform power-of-2 exponent E)
    float w;
    int   E = 0;
    if (role == 0) w = __expf(__ldg(startT + lane) + __ldg(emb + lane));   // alpha_0
    else           w = __expf(__ldg(endT + lane));                          // beta_1023

    // smem ping-pong addresses for this warp
    const unsigned sb  = (unsigned)__cvta_generic_to_shared(&sw[0][widx][0]);
    const unsigned ra0 = sb, ra1 = sb + 512;
    const unsigned wa0 = sb + lane * 4, wa1 = wa0 + 512;

    if (role == 0) { STSF(wa0, w) }                                            // w at s=0
    else { STSF(wa0, w * __expf(__ldg(emb + 1023 * T_SZ + lane))) }            // x_1023

    // lag-4 renorm scale from lane 0
    float sc_a; int k_a;
    {
        const float w0l = __shfl_sync(FULL, w, 0);
        const int   eb_ = (int)((__float_as_uint(w0l) >> 23) & 0xFF);
        sc_a = __uint_as_float((unsigned)(254 - eb_) << 23);   // 2^(127-eb)
        k_a  = eb_ - 127;
    }

    // depth-8 prefetch ring
    float eer[8], mkr[8];
    if (role == 0) {
#pragma unroll
        for (int k = 0; k < 8; ++k) {
            eer[k] = __expf(__ldg(emb + (1 + k) * T_SZ + lane));     // ee_s, s=1..8
            mkr[k] = __ldg(mb + 1 + k);
        }
    } else {
#pragma unroll
        for (int k = 0; k < 8; ++k) {
            eer[k] = __expf(__ldg(emb + (1022 - k) * T_SZ + lane));  // ee_{t-1}
            mkr[k] = __ldg(mb + 1023 - k);                           // m_t
        }
    }

    if (role == 0) {
        // forward: s = 1..512, 64 groups of 8 (prefetch overruns to <=520: valid, unused)
        for (int g = 0; g < 64; ++g) {
            const int s0 = 1 + g * 8;
            STEPF(0, ra0, wa1, false, s0 + 0)
            STEPF(1, ra1, wa0, false, s0 + 1)
            STEPF(2, ra0, wa1, false, s0 + 2)
            STEPF(3, ra1, wa0, true,  s0 + 3)
            STEPF(4, ra0, wa1, false, s0 + 4)
            STEPF(5, ra1, wa0, false, s0 + 5)
            STEPF(6, ra0, wa1, false, s0 + 6)
            STEPF(7, ra1, wa0, true,  s0 + 7)
        }
        // w = alpha_512 * 2^-E
    } else {
        // backward: t = 1023..513, 63 groups of 8 + 7-step tail
        for (int g = 0; g < 63; ++g) {
            const int t0 = 1023 - g * 8;
            STEPB(0, ra0, wa1, false, t0 - 0)
            STEPB(1, ra1, wa0, false, t0 - 1)
            STEPB(2, ra0, wa1, false, t0 - 2)
            STEPB(3, ra1, wa0, true,  t0 - 3)
            STEPB(4, ra0, wa1, false, t0 - 4)
            STEPB(5, ra1, wa0, false, t0 - 5)
            STEPB(6, ra0, wa1, false, t0 - 6)
            STEPB(7, ra1, wa0, true,  t0 - 7)
        }
        STEPB(0, ra0, wa1, false, 519)
        STEPB(1, ra1, wa0, false, 518)
        STEPB(2, ra0, wa1, false, 517)
        STEPB(3, ra1, wa0, true,  516)
        STEPB(4, ra0, wa1, false, 515)
        STEPB(5, ra1, wa0, false, 514)
        STEPB(6, ra0, wa1, false, 513)
        // w = beta_512 * 2^-E
        sxb[pair][lane] = w;
        if (lane == 0) sEb[pair] = E;
    }

    // ---- score: warp pair splits positions (stride 64) ----
    {
        const int* tb = tags + (size_t)b * S_SZ;
        float sacc = 0.f, msum = 0.f;
#pragma unroll 4
        for (int s = lane + 32 * role; s < S_SZ; s += 64) {
            const float mm = __ldg(mb + s);
            msum += mm;
            if (s == 0) {
                const int t0 = __ldg(tb) & (T_SZ - 1);
                sacc += __ldg(startT + t0) + __ldg(emb + t0);
            } else {
                const int tc = __ldg(tb + s)     & (T_SZ - 1);
                const int tp = __ldg(tb + s - 1) & (T_SZ - 1);
                sacc += (__ldg(emb + s * T_SZ + tc) + __ldg(trans + tp * T_SZ + tc)) * mm;
            }
        }
#pragma unroll
        for (int o = 16; o > 0; o >>= 1) {
            sacc += __shfl_xor_sync(FULL, sacc, o);
            msum += __shfl_xor_sync(FULL, msum, o);
        }
        if (lane == 0) { ssc[pair][role] = sacc; sms[pair][role] = msum; }
    }

    __syncthreads();

    // ---- forward warp combines: partition + score -> g_res[b] ----
    if (role == 0) {
        float v = w * sxb[pair][lane];
#pragma unroll
        for (int o = 16; o > 0; o >>= 1)
            v += __shfl_xor_sync(FULL, v, o);
        const float part = fmaf((float)(E + sEb[pair]), LN2F, __logf(v));

        if (lane == 0) {
            const int* tb = tags + (size_t)b * S_SZ;
            const float sacc = ssc[pair][0] + ssc[pair][1];
            const float msum = sms[pair][0] + sms[pair][1];
            int last = (int)msum - 1;
            last = last < 0 ? 0 : (last >= S_SZ ? S_SZ - 1 : last);
            const int tl = __ldg(tb + last) & (T_SZ - 1);
            g_res[b] = part - (sacc + __ldg(endT + tl));
        }
    }

    // ---- fused final reduction: last block to finish sums all 512 ----
    __syncthreads();
    __threadfence();
    if (threadIdx.x == 0)
        s_ticket = atomicAdd(&g_cnt, 1u);
    __syncthreads();

    if (s_ticket == gridDim.x - 1) {
        const int t = threadIdx.x;
        red[t] = g_res[t] + g_res[t + 128] + g_res[t + 256] + g_res[t + 384];
        __syncthreads();
#pragma unroll
        for (int st = 64; st > 0; st >>= 1) {
            if (t < st) red[t] += red[t + st];
            __syncthreads();
        }
        if (t == 0) { out[0] = red[0]; g_cnt = 0; }
    }
}

extern "C" void kernel_launch(void* const* d_in, const int* in_sizes, int n_in,
                              void* d_out, int out_size)
{
    const float* em     = (const float*)d_in[0];
    const int*   tags   = (const int*)d_in[1];
    const float* mask   = (const float*)d_in[2];
    const float* trans  = (const float*)d_in[3];
    const float* startT = (const float*)d_in[4];
    const float* endT   = (const float*)d_in[5];
    float* out = (float*)d_out;

    (void)in_sizes; (void)n_in; (void)out_size;

    // 256 blocks x 128 threads = 1024 warps: per batch, one forward warp
    // (512 steps) + one backward warp (511 steps) meeting at s=512
    crf_kernel<<<B_SZ / 2, 128>>>(em, tags, mask, trans, startT, endT, out);
}